// round 2
// baseline (speedup 1.0000x reference)
#include <cuda_runtime.h>
#include <cuda_bf16.h>

// Problem constants (from reference: VOCAB=32000, D_MODEL=512, BATCH=8, SEQ=4096)
constexpr int B_ = 8;
constexpr int S_ = 4096;
constexpr int D_ = 512;

// pe exponent constant: -(2/512)*log2(10000)
__device__ __forceinline__ float pe_val(float sf, int d) {
    const float C       = -0.05190512648261504f;  // -2/512 * log2(10000)
    const float INV2PI  =  0.15915494309189535f;
    const float PI2_HI  =  6.2831855f;            // fl32(2*pi)
    const float PI2_LO  = -1.7484556e-7f;         // 2*pi - PI2_HI
    const float PIO2    =  1.5707963267948966f;

    float w   = exp2f((float)d * C);              // 10000^(-2d/512)
    float off = (d & 1) ? PIO2 : 0.0f;            // odd d -> cos = sin(x + pi/2)
    float ang = fmaf(sf, w, off);
    float k   = rintf(ang * INV2PI);
    float r   = fmaf(k, -PI2_HI, ang);
    r         = fmaf(k, -PI2_LO, r);
    return __sinf(r);                             // |r| <= pi + eps -> accurate
}

__global__ __launch_bounds__(128) void emb_pe_kernel(
    const int*   __restrict__ tokens,   // [B, S]
    const float* __restrict__ table,    // [V, D]
    float*       __restrict__ out)      // [B, S, D]
{
    const int s = blockIdx.x;           // 0..4095
    const int t = threadIdx.x;          // 0..127
    const int d0 = t * 4;

    __shared__ int tok[B_];
    if (t < B_) tok[t] = tokens[t * S_ + s];

    // Positional-encoding float4 for columns d0..d0+3 (batch-invariant -> computed once per s)
    const float sf = (float)s;
    float4 pe4;
    pe4.x = pe_val(sf, d0 + 0);
    pe4.y = pe_val(sf, d0 + 1);
    pe4.z = pe_val(sf, d0 + 2);
    pe4.w = pe_val(sf, d0 + 3);

    __syncthreads();

    // 8 batch rows share this s: gather 2KB row, add PE, store. Fully unrolled
    // so the 8 LDG.128 can be in flight together (MLP ~8).
    #pragma unroll
    for (int b = 0; b < B_; b++) {
        const float4* __restrict__ row =
            reinterpret_cast<const float4*>(table + (size_t)tok[b] * D_);
        float4 v = __ldg(row + t);
        v.x += pe4.x;
        v.y += pe4.y;
        v.z += pe4.z;
        v.w += pe4.w;
        float4* __restrict__ dst =
            reinterpret_cast<float4*>(out + ((size_t)b * S_ + s) * D_);
        dst[t] = v;
    }
}

extern "C" void kernel_launch(void* const* d_in, const int* in_sizes, int n_in,
                              void* d_out, int out_size) {
    const int*   tokens = (const int*)d_in[0];     // [8, 4096] int32
    const float* table  = (const float*)d_in[1];   // [32000, 512] float32
    float*       out    = (float*)d_out;           // [8, 4096, 512] float32
    (void)in_sizes; (void)n_in; (void)out_size;

    emb_pe_kernel<<<S_, 128>>>(tokens, table, out);
}

// round 5
// speedup vs baseline: 1.1300x; 1.1300x over previous
#include <cuda_runtime.h>
#include <cuda_bf16.h>

// Problem constants (VOCAB=32000, D_MODEL=512, BATCH=8, SEQ=4096)
constexpr int B_ = 8;
constexpr int S_ = 4096;
constexpr int D_ = 512;

// pe[s,d] = sin(angle) for even d, cos(angle) for odd d,
// angle = s / 10000^(2d/512)  (per-index exponent, faithful to reference)
__device__ __forceinline__ float pe_val(float sf, int d) {
    const float C       = -0.05190512648261504f;  // -2/512 * log2(10000)
    const float INV2PI  =  0.15915494309189535f;
    const float PI2_HI  =  6.2831855f;            // fl32(2*pi)
    const float PI2_LO  = -1.7484556e-7f;         // 2*pi - PI2_HI
    const float PIO2    =  1.5707963267948966f;

    float w   = exp2f((float)d * C);              // 10000^(-2d/512)
    float off = (d & 1) ? PIO2 : 0.0f;            // odd d -> cos = sin(x + pi/2)
    float ang = fmaf(sf, w, off);
    float k   = rintf(ang * INV2PI);
    float r   = fmaf(k, -PI2_HI, ang);
    r         = fmaf(k, -PI2_LO, r);
    return __sinf(r);                             // |r| <= pi -> accurate
}

__global__ __launch_bounds__(128, 8) void emb_pe_kernel(
    const int*   __restrict__ tokens,   // [B, S]
    const float* __restrict__ table,    // [V, D]
    float*       __restrict__ out)      // [B, S, D]
{
    const int s = blockIdx.x;           // 0..4095
    const int t = threadIdx.x;          // 0..127

    // Uniform token loads: same address across the warp -> broadcast, 1 line
    // each. No smem, no barrier -- every warp's dependent token -> gather
    // chain starts immediately.
    int tok[B_];
    #pragma unroll
    for (int b = 0; b < B_; b++)
        tok[b] = __ldg(tokens + b * S_ + s);

    // Issue all 8 row gathers (MLP = 8 per thread) before touching the data.
    const float4* __restrict__ tab4 = reinterpret_cast<const float4*>(table);
    float4 v[B_];
    #pragma unroll
    for (int b = 0; b < B_; b++)
        v[b] = __ldg(tab4 + (size_t)tok[b] * (D_ / 4) + t);

    // Trig overlaps the in-flight gathers (batch-invariant per s).
    const float sf = (float)s;
    const int d0 = t * 4;
    float4 pe4;
    pe4.x = pe_val(sf, d0 + 0);
    pe4.y = pe_val(sf, d0 + 1);
    pe4.z = pe_val(sf, d0 + 2);
    pe4.w = pe_val(sf, d0 + 3);

    // Add + streaming store (.cs: output is never re-read; keep the table
    // resident in L2).
    float4* __restrict__ out4 = reinterpret_cast<float4*>(out);
    #pragma unroll
    for (int b = 0; b < B_; b++) {
        float4 r = v[b];
        r.x += pe4.x;
        r.y += pe4.y;
        r.z += pe4.z;
        r.w += pe4.w;
        __stcs(out4 + ((size_t)b * S_ + s) * (D_ / 4) + t, r);
    }
}

extern "C" void kernel_launch(void* const* d_in, const int* in_sizes, int n_in,
                              void* d_out, int out_size) {
    const int*   tokens = (const int*)d_in[0];     // [8, 4096] int32
    const float* table  = (const float*)d_in[1];   // [32000, 512] float32
    float*       out    = (float*)d_out;           // [8, 4096, 512] float32
    (void)in_sizes; (void)n_in; (void)out_size;

    emb_pe_kernel<<<S_, 128>>>(tokens, table, out);
}